// round 9
// baseline (speedup 1.0000x reference)
#include <cuda_runtime.h>
#include <cstdint>

#define BB 256
#define TT 199
#define QQ 1000
#define NROW (BB * TT)               // 50,944
#define NEL  ((size_t)NROW * QQ)     // 50,944,000

// Scratch (__device__ globals; zero at load; each use site resets its own
// counter before retiring, so every graph replay starts from zero).
__device__ float        g_rowbce[NROW];
__device__ float        g_partial[BB];
__device__ int          g_bt[BB];     // per-batch completion tickets
__device__ unsigned int g_done;       // batch-finalizer ticket

// One block per (b, t) row. Proven 82%-DRAM body; only the warp-0 epilogue
// changed (per-batch ticket finalize, no extra block-wide sync).
__global__ __launch_bounds__(256) void row_kernel(
    const float* __restrict__ pred,    // (B, T, Q)
    const float* __restrict__ batch,   // (B, T+1, Q)
    float* __restrict__ out)
{
    const int t   = blockIdx.x;
    const int b   = blockIdx.y;
    const int tid = threadIdx.x;
    const int lane = tid & 31;
    const int wid  = tid >> 5;

    const size_t row = (size_t)b * TT + t;
    const float* __restrict__ gt_row = batch + ((size_t)b * (TT + 1) + (t + 1)) * QQ;
    const float* __restrict__ p_row  = pred + row * QQ;

    __shared__ int   s_w[8];
    __shared__ float s_red[8];

    // ---- all 8 loads up front, unconditionally (max MLP) ----
    float g[4], p[4];
    #pragma unroll
    for (int k = 0; k < 4; k++) {
        int q = tid + 256 * k;
        bool valid = (k < 3) || (tid < QQ - 768);   // q < 1000
        g[k] = valid ? gt_row[q] : 0.0f;
        p[k] = valid ? p_row[q]  : 0.0f;
    }

    // ---- block-wide any(g == 1) ----
    int anyv = (g[0] == 1.0f) | (g[1] == 1.0f) | (g[2] == 1.0f) | (g[3] == 1.0f);
    unsigned wany = __ballot_sync(0xFFFFFFFFu, anyv);
    if (lane == 0) s_w[wid] = (wany != 0);
    __syncthreads();
    const int masked = s_w[0] | s_w[1] | s_w[2] | s_w[3] |
                       s_w[4] | s_w[5] | s_w[6] | s_w[7];
    const float fm = masked ? 1.0f : 0.0f;

    float* __restrict__ out_pred = out + 1 + row * QQ;
    float* __restrict__ out_gt   = out + 1 + NEL + row * QQ;

    float lsum = 0.0f;   // +(g*log p + (1-g)*log(1-p)); bce = -lsum
    #pragma unroll
    for (int k = 0; k < 4; k++) {
        int q = tid + 256 * k;
        bool valid = (k < 3) || (tid < QQ - 768);
        float pp = p[k], gg = g[k];
        float lp = fmaxf(__logf(pp),        -100.0f);
        float l1 = fmaxf(__logf(1.0f - pp), -100.0f);
        lsum += gg * lp + (1.0f - gg) * l1;
        if (valid) {
            out_pred[q] = pp * fm;
            out_gt[q]   = gg * fm;
        }
    }

    // ---- block reduction of lsum ----
    #pragma unroll
    for (int off = 16; off > 0; off >>= 1)
        lsum += __shfl_down_sync(0xFFFFFFFFu, lsum, off);
    if (lane == 0) s_red[wid] = lsum;
    __syncthreads();

    // ---- warp-0 epilogue: publish row, per-batch ticket, maybe finalize ----
    if (tid < 32) {
        float v = (tid < 8) ? s_red[tid] : 0.0f;
        #pragma unroll
        for (int off = 4; off > 0; off >>= 1)
            v += __shfl_down_sync(0xFFFFFFFFu, v, off);

        int done = 0;
        if (tid == 0) {
            g_rowbce[row] = fm * (-v);          // masked row => value >= ~10
            out[1 + 2 * NEL + row] = fm;        // row_mask as float 0/1
            __threadfence();                    // release: row publish < ticket
            done = atomicAdd(&g_bt[b], 1);
        }
        const int lastb = __shfl_sync(0xFFFFFFFFu, done, 0) == (TT - 1);

        if (lastb) {
            __threadfence();                    // acquire: see all 199 rows
            float sum = 0.0f; int cnt = 0;
            #pragma unroll
            for (int it = 0; it < 7; it++) {
                int tt = tid + 32 * it;
                if (tt < TT) {
                    float x = g_rowbce[b * TT + tt];
                    sum += x;
                    cnt += (x != 0.0f);
                }
            }
            #pragma unroll
            for (int off = 16; off > 0; off >>= 1) {
                sum += __shfl_down_sync(0xFFFFFFFFu, sum, off);
                cnt += __shfl_down_sync(0xFFFFFFFFu, cnt, off);
            }
            unsigned d2 = 0;
            if (tid == 0) {
                g_partial[b] = (cnt > 0)
                    ? (float)((double)sum / ((double)cnt * (double)QQ)) : 0.0f;
                g_bt[b] = 0;                    // reset for next replay
                __threadfence();                // release: partial < done-ticket
                d2 = atomicAdd(&g_done, 1u);
            }
            const int lastg = __shfl_sync(0xFFFFFFFFu, d2, 0) == (BB - 1);

            if (lastg) {
                __threadfence();                // acquire: see all partials
                float tot = 0.0f;
                #pragma unroll
                for (int j = 0; j < 8; j++)
                    tot += g_partial[tid + 32 * j];
                #pragma unroll
                for (int off = 16; off > 0; off >>= 1)
                    tot += __shfl_down_sync(0xFFFFFFFFu, tot, off);
                if (tid == 0) {
                    out[0] = tot;
                    g_done = 0u;                // reset for next replay
                }
            }
        }
    }
}

extern "C" void kernel_launch(void* const* d_in, const int* in_sizes, int n_in,
                              void* d_out, int out_size) {
    const float* pred  = (const float*)d_in[0];
    const float* batch = (const float*)d_in[1];
    float* out = (float*)d_out;

    dim3 grid(TT, BB);
    row_kernel<<<grid, 256>>>(pred, batch, out);
}

// round 10
// speedup vs baseline: 1.0522x; 1.0522x over previous
#include <cuda_runtime.h>
#include <cstdint>

#define BB 256
#define TT 199
#define QQ 1000
#define NROW (BB * TT)               // 50,944
#define NEL  ((size_t)NROW * QQ)     // 50,944,000

// Scratch (__device__ globals; zero at load; final_kernel resets them after
// reading, so every graph replay starts from zero). No fences anywhere:
// the kernel launch boundary orders row_kernel's atomics before final_kernel.
__device__ double g_bsum[BB];
__device__ int    g_bcnt[BB];

// ===== Proven hot-path body (117.5us, DRAM 82.1%) — loads/compute/stores
// byte-identical; epilogue now does 2 fire-and-forget per-batch atomics. =====
__global__ __launch_bounds__(256) void row_kernel(
    const float* __restrict__ pred,    // (B, T, Q)
    const float* __restrict__ batch,   // (B, T+1, Q)
    float* __restrict__ out)
{
    const int t   = blockIdx.x;
    const int b   = blockIdx.y;
    const int tid = threadIdx.x;
    const int lane = tid & 31;
    const int wid  = tid >> 5;

    const size_t row = (size_t)b * TT + t;
    const float* __restrict__ gt_row = batch + ((size_t)b * (TT + 1) + (t + 1)) * QQ;
    const float* __restrict__ p_row  = pred + row * QQ;

    __shared__ int   s_w[8];
    __shared__ float s_red[8];

    // ---- all 8 loads up front, unconditionally (max MLP) ----
    float g[4], p[4];
    #pragma unroll
    for (int k = 0; k < 4; k++) {
        int q = tid + 256 * k;
        bool valid = (k < 3) || (tid < QQ - 768);   // q < 1000
        g[k] = valid ? gt_row[q] : 0.0f;
        p[k] = valid ? p_row[q]  : 0.0f;
    }

    // ---- block-wide any(g == 1) ----
    int anyv = (g[0] == 1.0f) | (g[1] == 1.0f) | (g[2] == 1.0f) | (g[3] == 1.0f);
    unsigned wany = __ballot_sync(0xFFFFFFFFu, anyv);
    if (lane == 0) s_w[wid] = (wany != 0);
    __syncthreads();
    const int masked = s_w[0] | s_w[1] | s_w[2] | s_w[3] |
                       s_w[4] | s_w[5] | s_w[6] | s_w[7];
    const float fm = masked ? 1.0f : 0.0f;

    float* __restrict__ out_pred = out + 1 + row * QQ;
    float* __restrict__ out_gt   = out + 1 + NEL + row * QQ;

    float lsum = 0.0f;   // +(g*log p + (1-g)*log(1-p)); bce = -lsum
    #pragma unroll
    for (int k = 0; k < 4; k++) {
        int q = tid + 256 * k;
        bool valid = (k < 3) || (tid < QQ - 768);
        float pp = p[k], gg = g[k];
        float lp = fmaxf(__logf(pp),        -100.0f);
        float l1 = fmaxf(__logf(1.0f - pp), -100.0f);
        lsum += gg * lp + (1.0f - gg) * l1;
        if (valid) {
            out_pred[q] = pp * fm;
            out_gt[q]   = gg * fm;
        }
    }

    // ---- block reduction of lsum ----
    #pragma unroll
    for (int off = 16; off > 0; off >>= 1)
        lsum += __shfl_down_sync(0xFFFFFFFFu, lsum, off);
    if (lane == 0) s_red[wid] = lsum;
    __syncthreads();
    if (tid < 32) {
        float v = (tid < 8) ? s_red[tid] : 0.0f;
        #pragma unroll
        for (int off = 4; off > 0; off >>= 1)
            v += __shfl_down_sync(0xFFFFFFFFu, v, off);
        if (tid == 0) {
            out[1 + 2 * NEL + row] = fm;   // row_mask as float 0/1
            if (masked) {
                // fire-and-forget REDG; kernel boundary orders vs final_kernel
                atomicAdd(&g_bsum[b], (double)(-v));
                atomicAdd(&g_bcnt[b], 1);
            }
        }
    }
}

// ===== Tiny finalize: 1 block, 256 threads. Thread b handles batch b.
// Reads the per-batch accumulators, reduces, writes out[0], resets scratch.
__global__ __launch_bounds__(256) void final_kernel(float* __restrict__ out)
{
    const int b    = threadIdx.x;
    const int lane = b & 31;
    const int w    = b >> 5;

    __shared__ double s_d[8];

    const int    c = g_bcnt[b];
    const double s = g_bsum[b];
    double v = (c > 0) ? (s / ((double)c * (double)QQ)) : 0.0;

    // reset for next graph replay (deterministic)
    g_bsum[b] = 0.0;
    g_bcnt[b] = 0;

    #pragma unroll
    for (int off = 16; off > 0; off >>= 1)
        v += __shfl_down_sync(0xFFFFFFFFu, v, off);
    if (lane == 0) s_d[w] = v;
    __syncthreads();
    if (b < 8) {
        double x = s_d[b];
        #pragma unroll
        for (int off = 4; off > 0; off >>= 1)
            x += __shfl_down_sync(0xFFu, x, off);
        if (b == 0) out[0] = (float)x;
    }
}

extern "C" void kernel_launch(void* const* d_in, const int* in_sizes, int n_in,
                              void* d_out, int out_size) {
    const float* pred  = (const float*)d_in[0];
    const float* batch = (const float*)d_in[1];
    float* out = (float*)d_out;

    dim3 grid(TT, BB);
    row_kernel<<<grid, 256>>>(pred, batch, out);
    final_kernel<<<1, 256>>>(out);
}